// round 14
// baseline (speedup 1.0000x reference)
#include <cuda_runtime.h>
#include <cuda_bf16.h>
#include <math.h>

// Problem dims
#define BB 16
#define TT 512
#define II 256
#define HH 512
#define MM 2048
#define DD 64
#define NHD 4
#define OO 256
#define G4H 2048  // 4*H
#define EPSV 1e-8f

#define NWRK 128   // LSTM worker blocks (each owns 4 h-cols)
#define NTOT 129   // + 1 dedicated barrier-aggregator block (block 0)

// LSTM dynamic smem layout
#define HS2_BYTES  (HH * 8 * 8)        // 32768: h[k][b] as ull pairs
#define PART_BYTES (16 * 258 * 4)      // 16512: partials, padded stride
#define XS_BYTES   (II * BB * 4)       // 16384: x_t staged as [i][b]
#define LSTM_SMEM  (HS2_BYTES + PART_BYTES + 2 * XS_BYTES)  // 82048

// Fused-attention smem layout
#define KA_OFF   0
#define MS_OFF   (KA_OFF  + 64*132*4)
#define MS2_OFF  (MS_OFF  + 64*132*4)
#define PS_OFF   (MS2_OFF + 128*68*4)
#define IKN_OFF  (PS_OFF  + 128*132*4)
#define IMN_OFF  (IKN_OFF + 512)
#define LROW_OFF (IMN_OFF + 512)
#define LP_OFF   (LROW_OFF + 512)
#define ATT_SMEM (LP_OFF + 1024)           // = 172544

typedef unsigned long long ull;

// ---------------- scratch (static device globals; no runtime alloc) ------------
__device__ float g_hbuf[2][HH * BB];                  // [buf][k*16+b], double buffered
__device__ float g_combined[(size_t)BB * TT * (HH + NHD * DD)];  // [8192][768]
__device__ float g_keys[(size_t)BB * TT * NHD * DD];  // [32768][64]
__device__ float g_WhhT[HH * G4H];                    // [512][2048]
__device__ float g_WihT[II * G4H];                    // [256][2048]
__device__ float g_memnorm[MM];
__device__ volatile unsigned g_arrive[NTOT];          // flag barrier: per-block arrival
__device__ volatile unsigned g_release;               // flag barrier: release epoch

// ---------------- helpers ----------------
__device__ __forceinline__ float sigmoidf_(float x) {
    return 1.0f / (1.0f + __expf(-x));
}

__device__ __forceinline__ ull packf2(float a, float b) {
    ull r;
    asm("mov.b64 %0, {%1, %2};" : "=l"(r) : "f"(a), "f"(b));
    return r;
}
__device__ __forceinline__ void fma2(ull& d, ull a, ull b) {
    asm("fma.rn.f32x2 %0, %1, %2, %0;" : "+l"(d) : "l"(a), "l"(b));
}

__device__ __forceinline__ unsigned f2tf(float f) {
    unsigned r;
    asm("cvt.rna.tf32.f32 %0, %1;" : "=r"(r) : "f"(f));
    return r;
}

__device__ __forceinline__ void mma_tf32(float* c, const unsigned* a, const unsigned* b) {
    asm volatile(
        "mma.sync.aligned.m16n8k8.row.col.f32.tf32.tf32.f32 "
        "{%0,%1,%2,%3}, {%4,%5,%6,%7}, {%8,%9}, {%0,%1,%2,%3};"
        : "+f"(c[0]), "+f"(c[1]), "+f"(c[2]), "+f"(c[3])
        : "r"(a[0]), "r"(a[1]), "r"(a[2]), "r"(a[3]), "r"(b[0]), "r"(b[1]));
}

// Initial full grid barrier (R9 design, NTOT blocks; block 0 aggregates).
__device__ __forceinline__ void grid_bar_full(unsigned e, int tid, int bid) {
    __syncthreads();
    if (tid == 0) {
        __threadfence();
        g_arrive[bid] = e;
    }
    if (bid == 0) {
        if (tid < NTOT) {
            while (g_arrive[tid] != e) { }
        }
        __syncthreads();
        if (tid == 0) g_release = e;
    } else {
        if (tid == 0) {
            while (g_release != e) { }
        }
    }
    if (tid == 0) __threadfence();
    __syncthreads();
}

// ---------------- small prep kernels ----------------
__global__ void transpose_whh_kernel(const float* __restrict__ W_hh) {
    int idx = blockIdx.x * 256 + threadIdx.x;  // total 2048*512
    int g = idx & (G4H - 1);
    int k = idx >> 11;
    g_WhhT[k * G4H + g] = W_hh[g * HH + k];
}

__global__ void transpose_wih_kernel(const float* __restrict__ W_ih) {
    int idx = blockIdx.x * 256 + threadIdx.x;  // total 2048*256
    int g = idx & (G4H - 1);
    int i = idx >> 11;
    g_WihT[i * G4H + g] = W_ih[g * II + i];
}

__global__ void memnorm_kernel(const float* __restrict__ memory) {
    __shared__ float s[64];
    int m = blockIdx.x;
    float v = memory[m * DD + threadIdx.x];
    s[threadIdx.x] = v * v;
    __syncthreads();
    for (int o = 32; o > 0; o >>= 1) {
        if (threadIdx.x < o) s[threadIdx.x] += s[threadIdx.x + o];
        __syncthreads();
    }
    if (threadIdx.x == 0) g_memnorm[m] = sqrtf(s[0]);
}

// ---------------- tf32 tensor-core GEMM (unchanged) ----------------
template <bool BT, int BN, bool REMAP>
__global__ void __launch_bounds__(256) tgemm(
    const float* __restrict__ A, const float* __restrict__ B, float* __restrict__ C,
    int M, int N, int K, int lda, int ldb, int ldc,
    const float* __restrict__ bias1, const float* __restrict__ bias2)
{
    constexpr int WN = BN / 2;
    constexpr int NT = WN / 8;
    __shared__ unsigned As[2][16][132];
    __shared__ unsigned Bs[2][16][BN + 4];

    int tid = threadIdx.x;
    int wid = tid >> 5, lane = tid & 31;
    int wm = (wid >> 1) * 32;
    int wn = (wid & 1) * WN;
    int m0 = blockIdx.y * 128;
    int n0 = blockIdx.x * BN;
    int g = lane >> 2, tg = lane & 3;

    float acc[2][NT][4];
#pragma unroll
    for (int i = 0; i < 2; i++)
#pragma unroll
        for (int j = 0; j < NT; j++)
#pragma unroll
            for (int e = 0; e < 4; e++) acc[i][j][e] = 0.0f;

    int a_r = tid >> 1;
    int ak = (tid & 1) * 8;
    const float* Aptr = A + (size_t)(m0 + a_r) * lda + ak;

    const float* Bptr;
    int bn4 = 0, bk_nn = 0;
    if (BT) {
        Bptr = B + (size_t)(n0 + a_r) * ldb + ak;
    } else {
        bk_nn = tid >> 4;
        bn4 = (tid & 15) * 4;
        Bptr = B + (size_t)bk_nn * ldb + n0 + bn4;
    }

    int KT = K >> 4;

    {
        float4 a0 = *(const float4*)Aptr;
        float4 a1 = *(const float4*)(Aptr + 4);
        As[0][ak + 0][a_r] = f2tf(a0.x); As[0][ak + 1][a_r] = f2tf(a0.y);
        As[0][ak + 2][a_r] = f2tf(a0.z); As[0][ak + 3][a_r] = f2tf(a0.w);
        As[0][ak + 4][a_r] = f2tf(a1.x); As[0][ak + 5][a_r] = f2tf(a1.y);
        As[0][ak + 6][a_r] = f2tf(a1.z); As[0][ak + 7][a_r] = f2tf(a1.w);
        if (BT) {
            float4 b0 = *(const float4*)Bptr;
            float4 b1 = *(const float4*)(Bptr + 4);
            Bs[0][ak + 0][a_r] = f2tf(b0.x); Bs[0][ak + 1][a_r] = f2tf(b0.y);
            Bs[0][ak + 2][a_r] = f2tf(b0.z); Bs[0][ak + 3][a_r] = f2tf(b0.w);
            Bs[0][ak + 4][a_r] = f2tf(b1.x); Bs[0][ak + 5][a_r] = f2tf(b1.y);
            Bs[0][ak + 6][a_r] = f2tf(b1.z); Bs[0][ak + 7][a_r] = f2tf(b1.w);
        } else {
            float4 b0 = *(const float4*)Bptr;
            Bs[0][bk_nn][bn4 + 0] = f2tf(b0.x); Bs[0][bk_nn][bn4 + 1] = f2tf(b0.y);
            Bs[0][bk_nn][bn4 + 2] = f2tf(b0.z); Bs[0][bk_nn][bn4 + 3] = f2tf(b0.w);
        }
    }
    __syncthreads();

    for (int kt = 0; kt < KT; kt++) {
        int cur = kt & 1;
        float4 pa0, pa1, pb0, pb1;
        bool has_next = (kt + 1 < KT);
        if (has_next) {
            pa0 = *(const float4*)(Aptr + (kt + 1) * 16);
            pa1 = *(const float4*)(Aptr + (kt + 1) * 16 + 4);
            if (BT) {
                pb0 = *(const float4*)(Bptr + (kt + 1) * 16);
                pb1 = *(const float4*)(Bptr + (kt + 1) * 16 + 4);
            } else {
                pb0 = *(const float4*)(Bptr + (size_t)(kt + 1) * 16 * ldb);
            }
        }

#pragma unroll
        for (int ks = 0; ks < 2; ks++) {
            int kb = ks * 8;
            unsigned af[2][4];
#pragma unroll
            for (int mt = 0; mt < 2; mt++) {
                int row = wm + mt * 16;
                af[mt][0] = As[cur][kb + tg][row + g];
                af[mt][1] = As[cur][kb + tg][row + g + 8];
                af[mt][2] = As[cur][kb + tg + 4][row + g];
                af[mt][3] = As[cur][kb + tg + 4][row + g + 8];
            }
            unsigned bf[NT][2];
#pragma unroll
            for (int nt = 0; nt < NT; nt++) {
                bf[nt][0] = Bs[cur][kb + tg][wn + nt * 8 + g];
                bf[nt][1] = Bs[cur][kb + tg + 4][wn + nt * 8 + g];
            }
#pragma unroll
            for (int mt = 0; mt < 2; mt++)
#pragma unroll
                for (int nt = 0; nt < NT; nt++)
                    mma_tf32(acc[mt][nt], af[mt], bf[nt]);
        }

        if (has_next) {
            int nxt = cur ^ 1;
            As[nxt][ak + 0][a_r] = f2tf(pa0.x); As[nxt][ak + 1][a_r] = f2tf(pa0.y);
            As[nxt][ak + 2][a_r] = f2tf(pa0.z); As[nxt][ak + 3][a_r] = f2tf(pa0.w);
            As[nxt][ak + 4][a_r] = f2tf(pa1.x); As[nxt][ak + 5][a_r] = f2tf(pa1.y);
            As[nxt][ak + 6][a_r] = f2tf(pa1.z); As[nxt][ak + 7][a_r] = f2tf(pa1.w);
            if (BT) {
                Bs[nxt][ak + 0][a_r] = f2tf(pb0.x); Bs[nxt][ak + 1][a_r] = f2tf(pb0.y);
                Bs[nxt][ak + 2][a_r] = f2tf(pb0.z); Bs[nxt][ak + 3][a_r] = f2tf(pb0.w);
                Bs[nxt][ak + 4][a_r] = f2tf(pb1.x); Bs[nxt][ak + 5][a_r] = f2tf(pb1.y);
                Bs[nxt][ak + 6][a_r] = f2tf(pb1.z); Bs[nxt][ak + 7][a_r] = f2tf(pb1.w);
            } else {
                Bs[nxt][bk_nn][bn4 + 0] = f2tf(pb0.x); Bs[nxt][bk_nn][bn4 + 1] = f2tf(pb0.y);
                Bs[nxt][bk_nn][bn4 + 2] = f2tf(pb0.z); Bs[nxt][bk_nn][bn4 + 3] = f2tf(pb0.w);
            }
            __syncthreads();
        }
    }

#pragma unroll
    for (int mt = 0; mt < 2; mt++) {
        int r0 = m0 + wm + mt * 16 + g;
#pragma unroll
        for (int nt = 0; nt < NT; nt++) {
            int cc = n0 + wn + nt * 8 + tg * 2;
            float bv0 = 0.0f, bv1 = 0.0f;
            if (bias1) { bv0 += bias1[cc]; bv1 += bias1[cc + 1]; }
            if (bias2) { bv0 += bias2[cc]; bv1 += bias2[cc + 1]; }
            float2 v0 = make_float2(acc[mt][nt][0] + bv0, acc[mt][nt][1] + bv1);
            float2 v1 = make_float2(acc[mt][nt][2] + bv0, acc[mt][nt][3] + bv1);
            if (REMAP) {
                int ra = r0, rb2 = r0 + 8;
                size_t o0 = (size_t)(ra >> 2) * 768 + 512 + (ra & 3) * 64 + cc;
                size_t o1 = (size_t)(rb2 >> 2) * 768 + 512 + (rb2 & 3) * 64 + cc;
                *(float2*)&C[o0] = v0;
                *(float2*)&C[o1] = v1;
            } else {
                *(float2*)&C[(size_t)r0 * ldc + cc] = v0;
                *(float2*)&C[(size_t)(r0 + 8) * ldc + cc] = v1;
            }
        }
    }
}

// ---------------- fused attention kernel (unchanged) ----------------
__global__ void __launch_bounds__(256) attn_kernel(const float* __restrict__ memory) {
    extern __shared__ __align__(16) char sm[];
    unsigned (*Ka)[132]  = (unsigned(*)[132])(sm + KA_OFF);
    unsigned (*Ms)[132]  = (unsigned(*)[132])(sm + MS_OFF);
    unsigned (*Ms2)[68]  = (unsigned(*)[68])(sm + MS2_OFF);
    unsigned (*Ps)[132]  = (unsigned(*)[132])(sm + PS_OFF);
    float* ikn  = (float*)(sm + IKN_OFF);
    float* imn  = (float*)(sm + IMN_OFF);
    float* lrow = (float*)(sm + LROW_OFF);
    float (*lpart)[128] = (float(*)[128])(sm + LP_OFF);

    int tid = threadIdx.x;
    int wid = tid >> 5, lane = tid & 31;
    int g = lane >> 2, tg = lane & 3;
    int wm = (wid >> 1) * 32;
    int wn = (wid & 1) * 64;
    int wn2 = (wid & 1) * 32;
    int pbase = blockIdx.x * 128;

    {
        int row = tid >> 1;
        int f0 = (tid & 1) * 8;
        const float4* src = (const float4*)(g_keys + (size_t)(pbase + row) * DD) + f0;
        float ss = 0.0f;
#pragma unroll
        for (int i = 0; i < 8; i++) {
            float4 v = src[i];
            int k0 = (f0 + i) * 4;
            Ka[k0 + 0][row] = f2tf(v.x); Ka[k0 + 1][row] = f2tf(v.y);
            Ka[k0 + 2][row] = f2tf(v.z); Ka[k0 + 3][row] = f2tf(v.w);
            ss += v.x * v.x + v.y * v.y + v.z * v.z + v.w * v.w;
        }
        ss += __shfl_xor_sync(0xffffffffu, ss, 1);
        if ((tid & 1) == 0) ikn[row] = rsqrtf(ss);
        if (tid < 128) lrow[tid] = 0.0f;
    }

    float o[2][4][4];
#pragma unroll
    for (int mt = 0; mt < 2; mt++)
#pragma unroll
        for (int nt = 0; nt < 4; nt++)
#pragma unroll
            for (int e = 0; e < 4; e++) o[mt][nt][e] = 0.0f;

    for (int m0t = 0; m0t < MM; m0t += 128) {
        __syncthreads();

        {
            int slot = tid >> 1;
            int f0 = (tid & 1) * 8;
            const float4* src = (const float4*)(memory + (size_t)(m0t + slot) * DD) + f0;
#pragma unroll
            for (int i = 0; i < 8; i++) {
                float4 v = src[i];
                int k0 = (f0 + i) * 4;
                unsigned ua = f2tf(v.x), ub = f2tf(v.y), uc = f2tf(v.z), ud = f2tf(v.w);
                Ms[k0 + 0][slot] = ua; Ms[k0 + 1][slot] = ub;
                Ms[k0 + 2][slot] = uc; Ms[k0 + 3][slot] = ud;
                Ms2[slot][k0 + 0] = ua; Ms2[slot][k0 + 1] = ub;
                Ms2[slot][k0 + 2] = uc; Ms2[slot][k0 + 3] = ud;
            }
            if (tid < 128) imn[tid] = 1.0f / g_memnorm[m0t + tid];
        }
        __syncthreads();

        float s[2][8][4];
#pragma unroll
        for (int mt = 0; mt < 2; mt++)
#pragma unroll
            for (int nt = 0; nt < 8; nt++)
#pragma unroll
                for (int e = 0; e < 4; e++) s[mt][nt][e] = 0.0f;
#pragma unroll
        for (int kb = 0; kb < 64; kb += 8) {
            unsigned af[2][4];
#pragma unroll
            for (int mt = 0; mt < 2; mt++) {
                int row = wm + mt * 16;
                af[mt][0] = Ka[kb + tg][row + g];
                af[mt][1] = Ka[kb + tg][row + g + 8];
                af[mt][2] = Ka[kb + tg + 4][row + g];
                af[mt][3] = Ka[kb + tg + 4][row + g + 8];
            }
            unsigned bf[8][2];
#pragma unroll
            for (int nt = 0; nt < 8; nt++) {
                bf[nt][0] = Ms[kb + tg][wn + nt * 8 + g];
                bf[nt][1] = Ms[kb + tg + 4][wn + nt * 8 + g];
            }
#pragma unroll
            for (int mt = 0; mt < 2; mt++)
#pragma unroll
                for (int nt = 0; nt < 8; nt++)
                    mma_tf32(s[mt][nt], af[mt], bf[nt]);
        }

        float lp[4] = {0.0f, 0.0f, 0.0f, 0.0f};
#pragma unroll
        for (int mt = 0; mt < 2; mt++) {
            int r0 = wm + mt * 16 + g;
            float ka0 = ikn[r0], ka1 = ikn[r0 + 8];
#pragma unroll
            for (int nt = 0; nt < 8; nt++) {
                int c0 = wn + nt * 8 + tg * 2;
                float im0 = imn[c0], im1 = imn[c0 + 1];
                unsigned u00 = f2tf(__expf(s[mt][nt][0] * ka0 * im0));
                unsigned u01 = f2tf(__expf(s[mt][nt][1] * ka0 * im1));
                unsigned u10 = f2tf(__expf(s[mt][nt][2] * ka1 * im0));
                unsigned u11 = f2tf(__expf(s[mt][nt][3] * ka1 * im1));
                lp[mt * 2 + 0] += __uint_as_float(u00) + __uint_as_float(u01);
                lp[mt * 2 + 1] += __uint_as_float(u10) + __uint_as_float(u11);
                Ps[c0][r0] = u00;     Ps[c0 + 1][r0] = u01;
                Ps[c0][r0 + 8] = u10; Ps[c0 + 1][r0 + 8] = u11;
            }
        }
#pragma unroll
        for (int q = 0; q < 4; q++) {
            lp[q] += __shfl_xor_sync(0xffffffffu, lp[q], 1);
            lp[q] += __shfl_xor_sync(0xffffffffu, lp[q], 2);
        }
        if (tg == 0) {
#pragma unroll
            for (int mt = 0; mt < 2; mt++) {
                lpart[wid & 1][wm + mt * 16 + g] = lp[mt * 2 + 0];
                lpart[wid & 1][wm + mt * 16 + g + 8] = lp[mt * 2 + 1];
            }
        }
        __syncthreads();

        if (tid < 128) lrow[tid] += lpart[0][tid] + lpart[1][tid];

#pragma unroll 4
        for (int kb = 0; kb < 128; kb += 8) {
            unsigned af[2][4];
#pragma unroll
            for (int mt = 0; mt < 2; mt++) {
                int row = wm + mt * 16;
                af[mt][0] = Ps[kb + tg][row + g];
                af[mt][1] = Ps[kb + tg][row + g + 8];
                af[mt][2] = Ps[kb + tg + 4][row + g];
                af[mt][3] = Ps[kb + tg + 4][row + g + 8];
            }
            unsigned bf[4][2];
#pragma unroll
            for (int nt = 0; nt < 4; nt++) {
                bf[nt][0] = Ms2[kb + tg][wn2 + nt * 8 + g];
                bf[nt][1] = Ms2[kb + tg + 4][wn2 + nt * 8 + g];
            }
#pragma unroll
            for (int mt = 0; mt < 2; mt++)
#pragma unroll
                for (int nt = 0; nt < 4; nt++)
                    mma_tf32(o[mt][nt], af[mt], bf[nt]);
        }
    }

    __syncthreads();

#pragma unroll
    for (int mt = 0; mt < 2; mt++) {
        int r0 = wm + mt * 16 + g;
        float il0 = 1.0f / lrow[r0];
        float il1 = 1.0f / lrow[r0 + 8];
        int p0 = pbase + r0;
        int p1 = p0 + 8;
        size_t b0 = (size_t)(p0 >> 2) * 768 + 512 + (p0 & 3) * 64;
        size_t b1 = (size_t)(p1 >> 2) * 768 + 512 + (p1 & 3) * 64;
#pragma unroll
        for (int nt = 0; nt < 4; nt++) {
            int cc = wn2 + nt * 8 + tg * 2;
            float2 v0 = make_float2(o[mt][nt][0] * il0, o[mt][nt][1] * il0);
            float2 v1 = make_float2(o[mt][nt][2] * il1, o[mt][nt][3] * il1);
            *(float2*)&g_combined[b0 + cc] = v0;
            *(float2*)&g_combined[b1 + cc] = v1;
        }
    }
}

// ---------------- persistent LSTM kernel (x-GEMM folded in) ----------------
// 129 blocks: block 0 = dedicated barrier aggregator; blocks 1..128 = workers.
// Worker wbid owns h-cols wbid*4..+3 (16 gate cols). Per step:
//   arrive (posts h_{t-1} done) -> compute W_ih@x_t partials (x-only, hidden in
//   the wait) + issue x_{t+1} prefetch -> poll release -> stage h + x_{t+1} ->
//   W_hh@h partials added -> reduce + bias + activations -> write h_t.
// No separate pregates GEMM; pregates now fp32 (accuracy improves).
__global__ void __launch_bounds__(256) lstm_kernel(const float* __restrict__ x,
                                                   const float* __restrict__ b_ih,
                                                   const float* __restrict__ b_hh) {
    int tid = threadIdx.x;
    int bid = blockIdx.x;

    if (bid == 0) {
        // ---- aggregator ----
        unsigned e = g_release + 1;
        grid_bar_full(e, tid, bid);
        e++;
        for (unsigned k = 0; k < TT - 1; k++) {
            unsigned ep = e + k;
            if (tid < NWRK) {
                while (g_arrive[tid + 1] != ep) { }
            }
            __syncthreads();
            if (tid == 0) g_release = ep;
            __syncthreads();
        }
        return;
    }

    // ---- worker ----
    extern __shared__ __align__(16) char dynsm[];
    ull*   hs2     = (ull*)dynsm;                          // h[k][b] pairs, 32KB
    float* part_sm = (float*)(dynsm + HS2_BYTES);          // [c][ks*16+b], stride 258
    float* xsm0    = (float*)(dynsm + HS2_BYTES + PART_BYTES);
    float* xsm1    = (float*)(dynsm + HS2_BYTES + PART_BYTES + XS_BYTES);

    int wbid = bid - 1;

    int ks = tid >> 4;       // 0..15
    int c  = tid & 15;       // 0..15 gate-col within block
    int col = (c >> 2) * 512 + wbid * 4 + (c & 3);

    int uj = tid >> 4;       // update mapping (tid<64)
    int ub = tid & 15;

    // x-stage mapping: thread handles batch xb, i-range [xg*16, xg*16+16)
    int xb = tid & 15, xg = tid >> 4;

    float whreg[32];
#pragma unroll
    for (int kk = 0; kk < 32; kk++)
        whreg[kk] = g_WhhT[(size_t)(ks * 32 + kk) * G4H + col];
    float wireg[16];
#pragma unroll
    for (int ii = 0; ii < 16; ii++)
        wireg[ii] = g_WihT[(size_t)(ks * 16 + ii) * G4H + col];

    float bias[4];
    if (tid < 64) {
#pragma unroll
        for (int q = 0; q < 4; q++) {
            int bc = q * 512 + wbid * 4 + uj;
            bias[q] = b_ih[bc] + b_hh[bc];
        }
    }

    // stage x_0 into xsm0
    {
        const float4* src = (const float4*)(x + ((size_t)(xb * TT + 0)) * II + xg * 16);
        float4 v0 = src[0], v1 = src[1], v2 = src[2], v3 = src[3];
        float* d = xsm0 + xb;
        d[(xg * 16 + 0) * 16] = v0.x;  d[(xg * 16 + 1) * 16] = v0.y;
        d[(xg * 16 + 2) * 16] = v0.z;  d[(xg * 16 + 3) * 16] = v0.w;
        d[(xg * 16 + 4) * 16] = v1.x;  d[(xg * 16 + 5) * 16] = v1.y;
        d[(xg * 16 + 6) * 16] = v1.z;  d[(xg * 16 + 7) * 16] = v1.w;
        d[(xg * 16 + 8) * 16] = v2.x;  d[(xg * 16 + 9) * 16] = v2.y;
        d[(xg * 16 + 10) * 16] = v2.z; d[(xg * 16 + 11) * 16] = v2.w;
        d[(xg * 16 + 12) * 16] = v3.x; d[(xg * 16 + 13) * 16] = v3.y;
        d[(xg * 16 + 14) * 16] = v3.z; d[(xg * 16 + 15) * 16] = v3.w;
    }

    if (tid < 64) g_hbuf[1][wbid * 64 + tid] = 0.0f;
    float creg = 0.0f;

    unsigned e = g_release + 1;
    grid_bar_full(e, tid, bid);   // x_0 staged (syncthreads inside) + h init visible
    e++;                          // first main epoch

    for (int t = 0; t < TT; t++) {
        // ---- x-part: acc = W_ih[:, ks-range] @ x_t  (independent of h) ----
        ull acc[8];
#pragma unroll
        for (int p = 0; p < 8; p++) acc[p] = 0ULL;
        {
            const ull* xcur = (const ull*)((t & 1) ? xsm1 : xsm0);
#pragma unroll
            for (int ii = 0; ii < 16; ii++) {
                float w = wireg[ii];
                ull w2 = packf2(w, w);
                const ulonglong2* xp = (const ulonglong2*)(xcur + (size_t)(ks * 16 + ii) * 8);
                ulonglong2 x01 = xp[0], x23 = xp[1], x45 = xp[2], x67 = xp[3];
                fma2(acc[0], x01.x, w2);
                fma2(acc[1], x01.y, w2);
                fma2(acc[2], x23.x, w2);
                fma2(acc[3], x23.y, w2);
                fma2(acc[4], x45.x, w2);
                fma2(acc[5], x45.y, w2);
                fma2(acc[6], x67.x, w2);
                fma2(acc[7], x67.y, w2);
            }
        }

        // ---- prefetch x_{t+1} into regs ----
        float4 xr0, xr1, xr2, xr3;
        bool hasx = (t + 1 < TT);
        if (hasx) {
            const float4* src = (const float4*)(x + ((size_t)(xb * TT + t + 1)) * II + xg * 16);
            xr0 = src[0]; xr1 = src[1]; xr2 = src[2]; xr3 = src[3];
        }

        // ---- wait for h_{t-1} (epoch e+t-1), overlapped by the work above ----
        if (t > 0) {
            if (tid == 0) {
                unsigned ep = e + (unsigned)t - 1;
                while (g_release != ep) { }
                __threadfence();
            }
            __syncthreads();
        }

        // ---- stage h_{t-1} + store x_{t+1} ----
        {
            const float4* src = (const float4*)g_hbuf[(t & 1) ^ 1];
            float4* dst = (float4*)hs2;
#pragma unroll
            for (int i = 0; i < 8; i++) dst[tid + i * 256] = src[tid + i * 256];
        }
        if (hasx) {
            float* d = ((t & 1) ? xsm0 : xsm1) + xb;
            d[(xg * 16 + 0) * 16] = xr0.x;  d[(xg * 16 + 1) * 16] = xr0.y;
            d[(xg * 16 + 2) * 16] = xr0.z;  d[(xg * 16 + 3) * 16] = xr0.w;
            d[(xg * 16 + 4) * 16] = xr1.x;  d[(xg * 16 + 5) * 16] = xr1.y;
            d[(xg * 16 + 6) * 16] = xr1.z;  d[(xg * 16 + 7) * 16] = xr1.w;
            d[(xg * 16 + 8) * 16] = xr2.x;  d[(xg * 16 + 9) * 16] = xr2.y;
            d[(xg * 16 + 10) * 16] = xr2.z; d[(xg * 16 + 11) * 16] = xr2.w;
            d[(xg * 16 + 12) * 16] = xr3.x; d[(xg * 16 + 13) * 16] = xr3.y;
            d[(xg * 16 + 14) * 16] = xr3.z; d[(xg * 16 + 15) * 16] = xr3.w;
        }
        __syncthreads();

        // ---- h-part: acc += W_hh[:, ks-range] @ h_{t-1} ----
#pragma unroll
        for (int kk = 0; kk < 32; kk++) {
            int k = ks * 32 + kk;
            float w = whreg[kk];
            ull w2 = packf2(w, w);
            const ulonglong2* hp = (const ulonglong2*)(hs2 + (size_t)k * 8);
            ulonglong2 h01 = hp[0], h23 = hp[1], h45 = hp[2], h67 = hp[3];
            fma2(acc[0], h01.x, w2);
            fma2(acc[1], h01.y, w2);
            fma2(acc[2], h23.x, w2);
            fma2(acc[3], h23.y, w2);
            fma2(acc[4], h45.x, w2);
            fma2(acc[5], h45.y, w2);
            fma2(acc[6], h67.x, w2);
            fma2(acc[7], h67.y, w2);
        }
        {
            ull* pp = (ull*)&part_sm[c * 258 + ks * 16];
#pragma unroll
            for (int p = 0; p < 8; p++) pp[p] = acc[p];
        }
        __syncthreads();

        // ---- merged reduce + bias + activation + state update (64 threads) ----
        if (tid < 64) {
            float gv[4];
#pragma unroll
            for (int q = 0; q < 4; q++) {
                float s = bias[q];
                int base = (q * 4 + uj) * 258 + ub;
#pragma unroll
                for (int k2 = 0; k2 < 16; k2++)
                    s += part_sm[base + k2 * 16];
                gv[q] = s;
            }
            float ig = sigmoidf_(gv[0]);
            float fg = sigmoidf_(gv[1]);
            float gg = tanhf(gv[2]);
            float og = sigmoidf_(gv[3]);
            creg = fg * creg + ig * gg;
            float hn = og * tanhf(creg);
            int j = wbid * 4 + uj;
            g_hbuf[t & 1][j * 16 + ub] = hn;
            g_combined[((size_t)(ub * TT + t)) * 768 + j] = hn;
        }

        // ---- arrive (posts epoch e+t); last step needs no arrive ----
        if (t < TT - 1) {
            __syncthreads();
            if (tid == 0) {
                __threadfence();
                g_arrive[bid] = e + (unsigned)t;
            }
        }
    }
}

// ---------------- launch ----------------
extern "C" void kernel_launch(void* const* d_in, const int* in_sizes, int n_in,
                              void* d_out, int out_size) {
    const float* x      = (const float*)d_in[0];
    const float* memory = (const float*)d_in[1];
    const float* W_ih   = (const float*)d_in[2];
    const float* W_hh   = (const float*)d_in[3];
    const float* b_ih   = (const float*)d_in[4];
    const float* b_hh   = (const float*)d_in[5];
    const float* W_if   = (const float*)d_in[6];
    const float* b_if   = (const float*)d_in[7];
    const float* W_out  = (const float*)d_in[8];
    const float* b_out  = (const float*)d_in[9];
    float* out = (float*)d_out;

    float *comb, *keys;
    cudaGetSymbolAddress((void**)&comb, g_combined);
    cudaGetSymbolAddress((void**)&keys, g_keys);

    // opt-in to large dynamic smem (attribute calls, not allocations)
    cudaFuncSetAttribute(lstm_kernel, cudaFuncAttributeMaxDynamicSharedMemorySize, LSTM_SMEM);
    cudaFuncSetAttribute(attn_kernel, cudaFuncAttributeMaxDynamicSharedMemorySize, ATT_SMEM);

    // prep
    transpose_whh_kernel<<<(G4H * HH) / 256, 256>>>(W_hh);
    transpose_wih_kernel<<<(G4H * II) / 256, 256>>>(W_ih);
    memnorm_kernel<<<MM, 64>>>(memory);

    // LSTM recurrence with folded input GEMM (persistent; 129 blocks:
    // 1 aggregator + 128 workers; 1 flag-barrier/step hidden behind x-GEMM)
    lstm_kernel<<<NTOT, 256, LSTM_SMEM>>>(x, b_ih, b_hh);

    // keys: [8192,256] = hs(combined[:, :512], lda=768) @ W_if[:256]^T + b_if[:256]
    tgemm<true, 128, false><<<dim3(256 / 128, (BB * TT) / 128), 256>>>(
        comb, W_if, keys, BB * TT, NHD * DD, HH, 768, HH, NHD * DD, b_if, nullptr);

    // fused attention: sims + softmax + reads in one kernel, writes combined[:,512:]
    attn_kernel<<<(BB * TT * NHD) / 128, 256, ATT_SMEM>>>(memory);

    // out: [8192,256] = combined[8192,768] @ W_out^T + b_out
    tgemm<true, 128, false><<<dim3(OO / 128, (BB * TT) / 128), 256>>>(
        comb, W_out, out, BB * TT, OO, HH + NHD * DD, 768, 768, OO, b_out, nullptr);
}